// round 5
// baseline (speedup 1.0000x reference)
#include <cuda_runtime.h>
#include <math.h>

#define BB   8
#define NN   2048
#define KK   16
#define CIN  128
#define HID  128
#define COUT 128
#define NNODE (BB * NN)
#define PN   8     // nodes per block in precompute
#define PBN  4     // nodes per block in main kernel
#define ROWP 20    // padded x1T row length (floats): 4-way STS floor, 16B-aligned reads

// scratch: per-node projections  A = h@(W1a-W1b)+b1,  U = h@W1b
__device__ float g_A[NNODE * HID];
__device__ float g_U[NNODE * HID];
__device__ int   g_idx_is64;

// ---- f32x2 packed-math helpers ----
__device__ __forceinline__ unsigned long long ffma2(unsigned long long a,
                                                    unsigned long long b,
                                                    unsigned long long c) {
    unsigned long long d;
    asm("fma.rn.f32x2 %0, %1, %2, %3;" : "=l"(d) : "l"(a), "l"(b), "l"(c));
    return d;
}
__device__ __forceinline__ unsigned long long pack2(float lo, float hi) {
    unsigned long long v;
    asm("mov.b64 %0, {%1, %2};" : "=l"(v) : "f"(lo), "f"(hi));
    return v;
}
__device__ __forceinline__ float2 unpack2(unsigned long long v) {
    float2 r;
    asm("mov.b64 {%0, %1}, %2;" : "=f"(r.x), "=f"(r.y) : "l"(v));
    return r;
}

__global__ void detect_idx_kernel(const int* __restrict__ idx_raw) {
    if (threadIdx.x < 32) {
        int nz = (idx_raw[2 * threadIdx.x + 1] != 0) |
                 (idx_raw[2 * (threadIdx.x + 32) + 1] != 0);
        unsigned m = __ballot_sync(0xffffffffu, nz);
        if (threadIdx.x == 0) g_idx_is64 = (m == 0u);
    }
}

__device__ __forceinline__ float gelu_exact(float x) {
    return 0.5f * x * (1.0f + erff(x * 0.70710678118654752440f));
}

// ---------------------------------------------------------------------------
// Precompute A = h@(W1a-W1b)+b1,  U = h@W1b   (f32x2 packed along d)
// ---------------------------------------------------------------------------
__global__ __launch_bounds__(128) void precompute_kernel(
    const float* __restrict__ h,
    const float* __restrict__ W1,
    const float* __restrict__ b1)
{
    __shared__ float hs[PN][CIN];
    const int t     = threadIdx.x;
    const int node0 = blockIdx.x * PN;

    #pragma unroll
    for (int i = 0; i < PN; ++i)
        hs[i][t] = h[(size_t)(node0 + i) * CIN + t];
    __syncthreads();

    unsigned long long accA[PN], accU[PN];
    #pragma unroll
    for (int i = 0; i < PN; ++i) { accA[i] = 0ull; accU[i] = 0ull; }

    #pragma unroll 2
    for (int dd = 0; dd < CIN / 4; ++dd) {
        const int d0 = 4 * dd;
        float w1a[4], w1b[4];
        #pragma unroll
        for (int j = 0; j < 4; ++j) {
            w1a[j] = W1[(d0 + j) * HID + t];
            w1b[j] = W1[(CIN + d0 + j) * HID + t];
        }
        const unsigned long long wa01 = pack2(w1a[0] - w1b[0], w1a[1] - w1b[1]);
        const unsigned long long wa23 = pack2(w1a[2] - w1b[2], w1a[3] - w1b[3]);
        const unsigned long long wb01 = pack2(w1b[0], w1b[1]);
        const unsigned long long wb23 = pack2(w1b[2], w1b[3]);
        #pragma unroll
        for (int i = 0; i < PN; ++i) {
            const ulonglong2 m2 = *reinterpret_cast<const ulonglong2*>(&hs[i][d0]);
            accA[i] = ffma2(m2.x, wa01, accA[i]);
            accA[i] = ffma2(m2.y, wa23, accA[i]);
            accU[i] = ffma2(m2.x, wb01, accU[i]);
            accU[i] = ffma2(m2.y, wb23, accU[i]);
        }
    }
    const float bv = b1[t];
    #pragma unroll
    for (int i = 0; i < PN; ++i) {
        const float2 a2 = unpack2(accA[i]);
        const float2 u2 = unpack2(accU[i]);
        g_A[(size_t)(node0 + i) * HID + t] = a2.x + a2.y + bv;
        g_U[(size_t)(node0 + i) * HID + t] = u2.x + u2.y;
    }
}

// ---------------------------------------------------------------------------
// Main kernel: 4 nodes per block (128 threads).
// Phase A (thread = channel d): build x1 transposed x1T[node][d][k].
// Phase B (warp = node, lane = 4 columns): GEMM2 with f32x2 packed over k,
//         in-warp epilogue (bias, gelu, max over k, LayerNorm).
// ---------------------------------------------------------------------------
__global__ __launch_bounds__(128, 4) void edgeconv_kernel(
    const float* __restrict__ pos,
    const int*   __restrict__ idx_raw,
    const float* __restrict__ W1,      // rows 256..258 (rel weights)
    const float* __restrict__ W2,      // (HID, COUT) row-major
    const float* __restrict__ b2,
    const float* __restrict__ gamma,
    const float* __restrict__ beta,
    float*       __restrict__ out)
{
    __shared__ float x1t[PBN][HID][ROWP];   // 40 KB
    __shared__ int   jidx[PBN][KK];
    __shared__ float rel_s[PBN][KK][4];

    const int t     = threadIdx.x;
    const int node0 = blockIdx.x * PBN;

    // ---- neighbor indices for all 4 nodes ----
    if (t < PBN * KK) {
        const int nn = t >> 4, k = t & 15;
        const int is64 = g_idx_is64;
        long e = (long)(node0 + nn) * KK + k;
        jidx[nn][k] = is64 ? idx_raw[2 * e] : idx_raw[e];
    }
    __syncthreads();

    // ---- relative positions for all 4 nodes ----
    for (int s = t; s < PBN * 3 * KK; s += 128) {
        const int nn = s / (3 * KK);
        const int r  = s - nn * 3 * KK;
        const int k  = r / 3, c = r - 3 * k;
        const int node = node0 + nn;
        const int b = node >> 11, n = node & (NN - 1);
        const float* pb = pos + (size_t)b * NN * 3;
        rel_s[nn][k][c] = pb[jidx[nn][k] * 3 + c] - pb[n * 3 + c];
    }
    __syncthreads();

    // ---- phase A: x1T for each node (thread t = channel d) ----
    const float wc0 = W1[(2 * CIN + 0) * HID + t];
    const float wc1 = W1[(2 * CIN + 1) * HID + t];
    const float wc2 = W1[(2 * CIN + 2) * HID + t];

    #pragma unroll 1
    for (int nn = 0; nn < PBN; ++nn) {
        const int node = node0 + nn;
        const int b = node >> 11;
        const float a = g_A[(size_t)node * HID + t];
        float v[KK];
        #pragma unroll
        for (int k = 0; k < KK; ++k) {
            const float uk = g_U[((size_t)b * NN + jidx[nn][k]) * HID + t];
            float x = a + uk;
            x = fmaf(rel_s[nn][k][0], wc0, x);
            x = fmaf(rel_s[nn][k][1], wc1, x);
            x = fmaf(rel_s[nn][k][2], wc2, x);
            v[k] = gelu_exact(x);
        }
        #pragma unroll
        for (int g = 0; g < 4; ++g)
            *reinterpret_cast<float4*>(&x1t[nn][t][4 * g]) =
                make_float4(v[4 * g], v[4 * g + 1], v[4 * g + 2], v[4 * g + 3]);
    }
    __syncthreads();

    // ---- phase B: GEMM2, one warp per node ----
    const int nn   = t >> 5;          // node-warp
    const int lane = t & 31;
    const int c0   = lane * 4;
    const int node = node0 + nn;

    unsigned long long acc[8][4];     // [k-pair][column]
    #pragma unroll
    for (int kp = 0; kp < 8; ++kp)
        #pragma unroll
        for (int ci = 0; ci < 4; ++ci) acc[kp][ci] = 0ull;

    #pragma unroll 2
    for (int dd = 0; dd < HID / 4; ++dd) {
        #pragma unroll
        for (int j = 0; j < 4; ++j) {
            const int d = 4 * dd + j;
            const float4 w = *reinterpret_cast<const float4*>(&W2[d * COUT + c0]);
            unsigned long long wp[4];
            wp[0] = pack2(w.x, w.x);
            wp[1] = pack2(w.y, w.y);
            wp[2] = pack2(w.z, w.z);
            wp[3] = pack2(w.w, w.w);
            const ulonglong2* row = reinterpret_cast<const ulonglong2*>(&x1t[nn][d][0]);
            #pragma unroll
            for (int j2 = 0; j2 < 4; ++j2) {
                const ulonglong2 p = row[j2];   // k = 4*j2 .. 4*j2+3 (two packed pairs)
                #pragma unroll
                for (int ci = 0; ci < 4; ++ci) {
                    acc[2 * j2 + 0][ci] = ffma2(p.x, wp[ci], acc[2 * j2 + 0][ci]);
                    acc[2 * j2 + 1][ci] = ffma2(p.y, wp[ci], acc[2 * j2 + 1][ci]);
                }
            }
        }
    }

    // ---- epilogue: bias + gelu + max over 16 k (in-thread) ----
    const float4 bv = *reinterpret_cast<const float4*>(&b2[c0]);
    const float bb[4] = {bv.x, bv.y, bv.z, bv.w};
    float vmax[4] = {-INFINITY, -INFINITY, -INFINITY, -INFINITY};
    #pragma unroll
    for (int kp = 0; kp < 8; ++kp)
        #pragma unroll
        for (int ci = 0; ci < 4; ++ci) {
            const float2 p = unpack2(acc[kp][ci]);
            vmax[ci] = fmaxf(vmax[ci], gelu_exact(p.x + bb[ci]));
            vmax[ci] = fmaxf(vmax[ci], gelu_exact(p.y + bb[ci]));
        }

    // ---- LayerNorm within the warp (lane holds 4 channels) ----
    float s = vmax[0] + vmax[1] + vmax[2] + vmax[3];
    #pragma unroll
    for (int o = 16; o > 0; o >>= 1) s += __shfl_xor_sync(0xffffffffu, s, o);
    const float mean = s * (1.0f / COUT);

    float dv[4];
    float q = 0.0f;
    #pragma unroll
    for (int ci = 0; ci < 4; ++ci) {
        dv[ci] = vmax[ci] - mean;
        q = fmaf(dv[ci], dv[ci], q);
    }
    #pragma unroll
    for (int o = 16; o > 0; o >>= 1) q += __shfl_xor_sync(0xffffffffu, q, o);
    const float rstd = rsqrtf(q * (1.0f / COUT) + 1e-5f);

    const float4 g4 = *reinterpret_cast<const float4*>(&gamma[c0]);
    const float4 be4 = *reinterpret_cast<const float4*>(&beta[c0]);
    float4 o4;
    o4.x = dv[0] * rstd * g4.x + be4.x;
    o4.y = dv[1] * rstd * g4.y + be4.y;
    o4.z = dv[2] * rstd * g4.z + be4.z;
    o4.w = dv[3] * rstd * g4.w + be4.w;
    *reinterpret_cast<float4*>(&out[(size_t)node * COUT + c0]) = o4;
}

extern "C" void kernel_launch(void* const* d_in, const int* in_sizes, int n_in,
                              void* d_out, int out_size) {
    const float* h     = (const float*)d_in[0];
    const float* pos   = (const float*)d_in[1];
    const int*   idx   = (const int*)  d_in[2];
    const float* W1    = (const float*)d_in[3];
    const float* b1    = (const float*)d_in[4];
    const float* W2    = (const float*)d_in[5];
    const float* b2    = (const float*)d_in[6];
    const float* gamma = (const float*)d_in[7];
    const float* beta  = (const float*)d_in[8];
    float*       out   = (float*)d_out;

    detect_idx_kernel<<<1, 32>>>(idx);
    precompute_kernel<<<NNODE / PN, 128>>>(h, W1, b1);
    edgeconv_kernel<<<NNODE / PBN, 128>>>(pos, idx, W1, W2, b2, gamma, beta, out);
}

// round 6
// speedup vs baseline: 1.5198x; 1.5198x over previous
#include <cuda_runtime.h>
#include <math.h>

#define BB   8
#define NN   2048
#define KK   16
#define CIN  128
#define HID  128
#define COUT 128
#define NNODE (BB * NN)
#define PN   8     // nodes per block in precompute
#define PBN  2     // nodes per block in main kernel
#define ROWP 20    // padded x1t row length (floats)

// scratch: per-node projections  A = h@(W1a-W1b)+b1,  U = h@W1b
__device__ float g_A[NNODE * HID];
__device__ float g_U[NNODE * HID];
__device__ int   g_idx_is64;

// ---- f32x2 packed-math helpers ----
__device__ __forceinline__ unsigned long long ffma2(unsigned long long a,
                                                    unsigned long long b,
                                                    unsigned long long c) {
    unsigned long long d;
    asm("fma.rn.f32x2 %0, %1, %2, %3;" : "=l"(d) : "l"(a), "l"(b), "l"(c));
    return d;
}
__device__ __forceinline__ unsigned long long pack2(float lo, float hi) {
    unsigned long long v;
    asm("mov.b64 %0, {%1, %2};" : "=l"(v) : "f"(lo), "f"(hi));
    return v;
}
__device__ __forceinline__ float2 unpack2(unsigned long long v) {
    float2 r;
    asm("mov.b64 {%0, %1}, %2;" : "=f"(r.x), "=f"(r.y) : "l"(v));
    return r;
}

__global__ void detect_idx_kernel(const int* __restrict__ idx_raw) {
    if (threadIdx.x < 32) {
        int nz = (idx_raw[2 * threadIdx.x + 1] != 0) |
                 (idx_raw[2 * (threadIdx.x + 32) + 1] != 0);
        unsigned m = __ballot_sync(0xffffffffu, nz);
        if (threadIdx.x == 0) g_idx_is64 = (m == 0u);
    }
}

__device__ __forceinline__ float gelu_exact(float x) {
    return 0.5f * x * (1.0f + erff(x * 0.70710678118654752440f));
}

// ---------------------------------------------------------------------------
// Precompute A = h@(W1a-W1b)+b1,  U = h@W1b   (f32x2 packed along d)
// ---------------------------------------------------------------------------
__global__ __launch_bounds__(128) void precompute_kernel(
    const float* __restrict__ h,
    const float* __restrict__ W1,
    const float* __restrict__ b1)
{
    __shared__ float hs[PN][CIN];
    const int t     = threadIdx.x;
    const int node0 = blockIdx.x * PN;

    #pragma unroll
    for (int i = 0; i < PN; ++i)
        hs[i][t] = h[(size_t)(node0 + i) * CIN + t];
    __syncthreads();

    unsigned long long accA[PN], accU[PN];
    #pragma unroll
    for (int i = 0; i < PN; ++i) { accA[i] = 0ull; accU[i] = 0ull; }

    #pragma unroll 2
    for (int dd = 0; dd < CIN / 4; ++dd) {
        const int d0 = 4 * dd;
        float w1a[4], w1b[4];
        #pragma unroll
        for (int j = 0; j < 4; ++j) {
            w1a[j] = W1[(d0 + j) * HID + t];
            w1b[j] = W1[(CIN + d0 + j) * HID + t];
        }
        const unsigned long long wa01 = pack2(w1a[0] - w1b[0], w1a[1] - w1b[1]);
        const unsigned long long wa23 = pack2(w1a[2] - w1b[2], w1a[3] - w1b[3]);
        const unsigned long long wb01 = pack2(w1b[0], w1b[1]);
        const unsigned long long wb23 = pack2(w1b[2], w1b[3]);
        #pragma unroll
        for (int i = 0; i < PN; ++i) {
            const ulonglong2 m2 = *reinterpret_cast<const ulonglong2*>(&hs[i][d0]);
            accA[i] = ffma2(m2.x, wa01, accA[i]);
            accA[i] = ffma2(m2.y, wa23, accA[i]);
            accU[i] = ffma2(m2.x, wb01, accU[i]);
            accU[i] = ffma2(m2.y, wb23, accU[i]);
        }
    }
    const float bv = b1[t];
    #pragma unroll
    for (int i = 0; i < PN; ++i) {
        const float2 a2 = unpack2(accA[i]);
        const float2 u2 = unpack2(accU[i]);
        g_A[(size_t)(node0 + i) * HID + t] = a2.x + a2.y + bv;
        g_U[(size_t)(node0 + i) * HID + t] = u2.x + u2.y;
    }
}

// ---------------------------------------------------------------------------
// Main kernel: 2 nodes per block (128 threads).
// Phase A (thread = channel d): x1 transposed, k-major: x1t[nn][d][k].
// Phase B (64 threads per node): thread owns 2 cols x ALL 16 k, FFMA2 over
//         k-pairs; in-thread max over k; 2-warp LayerNorm.
// ---------------------------------------------------------------------------
__global__ __launch_bounds__(128, 6) void edgeconv_kernel(
    const float* __restrict__ pos,
    const int*   __restrict__ idx_raw,
    const float* __restrict__ W1,      // rows 256..258 (rel weights)
    const float* __restrict__ W2,      // (HID, COUT) row-major
    const float* __restrict__ b2,
    const float* __restrict__ gamma,
    const float* __restrict__ beta,
    float*       __restrict__ out)
{
    __shared__ float x1t[PBN][HID][ROWP];   // 2*128*20*4 = 20 KB
    __shared__ int   jidx[PBN][KK];
    __shared__ float rel_s[PBN][KK][4];
    __shared__ float red_s[PBN][2][2];      // [node][stat][warp-in-node]

    const int t     = threadIdx.x;
    const int node0 = blockIdx.x * PBN;

    // ---- neighbor indices ----
    if (t < PBN * KK) {
        const int nn = t >> 4, k = t & 15;
        const int is64 = g_idx_is64;
        long e = (long)(node0 + nn) * KK + k;
        jidx[nn][k] = is64 ? idx_raw[2 * e] : idx_raw[e];
    }
    __syncthreads();

    // ---- relative positions ----
    if (t < PBN * 3 * KK) {
        const int nn = t / (3 * KK);
        const int r  = t - nn * 3 * KK;
        const int k  = r / 3, c = r - 3 * k;
        const int node = node0 + nn;
        const int b = node >> 11, n = node & (NN - 1);
        const float* pb = pos + (size_t)b * NN * 3;
        rel_s[nn][k][c] = pb[jidx[nn][k] * 3 + c] - pb[n * 3 + c];
    }
    __syncthreads();

    // ---- phase A: x1t (thread t = channel d) ----
    const float wc0 = W1[(2 * CIN + 0) * HID + t];
    const float wc1 = W1[(2 * CIN + 1) * HID + t];
    const float wc2 = W1[(2 * CIN + 2) * HID + t];

    #pragma unroll
    for (int nn = 0; nn < PBN; ++nn) {
        const int node = node0 + nn;
        const int b = node >> 11;
        const float a = g_A[(size_t)node * HID + t];
        float v[KK];
        #pragma unroll
        for (int k = 0; k < KK; ++k) {
            const float uk = g_U[((size_t)b * NN + jidx[nn][k]) * HID + t];
            float x = a + uk;
            x = fmaf(rel_s[nn][k][0], wc0, x);
            x = fmaf(rel_s[nn][k][1], wc1, x);
            x = fmaf(rel_s[nn][k][2], wc2, x);
            v[k] = gelu_exact(x);
        }
        #pragma unroll
        for (int g = 0; g < 4; ++g)
            *reinterpret_cast<float4*>(&x1t[nn][t][4 * g]) =
                make_float4(v[4 * g], v[4 * g + 1], v[4 * g + 2], v[4 * g + 3]);
    }
    __syncthreads();

    // ---- phase B: GEMM2, 64 threads per node, 2 cols x 16 k per thread ----
    const int nn   = t >> 6;          // node within block
    const int u    = t & 63;
    const int c0   = 2 * u;
    const int node = node0 + nn;

    unsigned long long acc[8][2];     // [k-pair][col]
    #pragma unroll
    for (int kp = 0; kp < 8; ++kp) { acc[kp][0] = 0ull; acc[kp][1] = 0ull; }

    #pragma unroll 2
    for (int dd = 0; dd < HID / 4; ++dd) {
        #pragma unroll
        for (int j = 0; j < 4; ++j) {
            const int d = 4 * dd + j;
            const float2 w = *reinterpret_cast<const float2*>(&W2[d * COUT + c0]);
            const unsigned long long wpA = pack2(w.x, w.x);
            const unsigned long long wpB = pack2(w.y, w.y);
            const ulonglong2* row = reinterpret_cast<const ulonglong2*>(&x1t[nn][d][0]);
            #pragma unroll
            for (int j2 = 0; j2 < 4; ++j2) {
                const ulonglong2 p = row[j2];   // k-pairs 2*j2, 2*j2+1
                acc[2 * j2 + 0][0] = ffma2(p.x, wpA, acc[2 * j2 + 0][0]);
                acc[2 * j2 + 0][1] = ffma2(p.x, wpB, acc[2 * j2 + 0][1]);
                acc[2 * j2 + 1][0] = ffma2(p.y, wpA, acc[2 * j2 + 1][0]);
                acc[2 * j2 + 1][1] = ffma2(p.y, wpB, acc[2 * j2 + 1][1]);
            }
        }
    }

    // ---- epilogue: bias + gelu + max over all 16 k (in-thread) ----
    const float2 bv = *reinterpret_cast<const float2*>(&b2[c0]);
    float v0 = -INFINITY, v1 = -INFINITY;
    #pragma unroll
    for (int kp = 0; kp < 8; ++kp) {
        const float2 p0 = unpack2(acc[kp][0]);
        const float2 p1 = unpack2(acc[kp][1]);
        v0 = fmaxf(v0, gelu_exact(p0.x + bv.x));
        v0 = fmaxf(v0, gelu_exact(p0.y + bv.x));
        v1 = fmaxf(v1, gelu_exact(p1.x + bv.y));
        v1 = fmaxf(v1, gelu_exact(p1.y + bv.y));
    }

    // ---- LayerNorm over 128 channels = 64 threads (2 warps) per node ----
    const int winn = (t >> 5) & 1;    // warp within node
    float s = v0 + v1;
    #pragma unroll
    for (int o = 16; o > 0; o >>= 1) s += __shfl_xor_sync(0xffffffffu, s, o);
    if ((t & 31) == 0) red_s[nn][0][winn] = s;
    __syncthreads();
    const float mean = (red_s[nn][0][0] + red_s[nn][0][1]) * (1.0f / COUT);

    const float d0v = v0 - mean, d1v = v1 - mean;
    float q = d0v * d0v + d1v * d1v;
    #pragma unroll
    for (int o = 16; o > 0; o >>= 1) q += __shfl_xor_sync(0xffffffffu, q, o);
    if ((t & 31) == 0) red_s[nn][1][winn] = q;
    __syncthreads();
    const float var  = (red_s[nn][1][0] + red_s[nn][1][1]) * (1.0f / COUT);
    const float rstd = rsqrtf(var + 1e-5f);

    const float2 g2 = *reinterpret_cast<const float2*>(&gamma[c0]);
    const float2 be2 = *reinterpret_cast<const float2*>(&beta[c0]);
    float2 o2;
    o2.x = d0v * rstd * g2.x + be2.x;
    o2.y = d1v * rstd * g2.y + be2.y;
    *reinterpret_cast<float2*>(&out[(size_t)node * COUT + c0]) = o2;
}

extern "C" void kernel_launch(void* const* d_in, const int* in_sizes, int n_in,
                              void* d_out, int out_size) {
    const float* h     = (const float*)d_in[0];
    const float* pos   = (const float*)d_in[1];
    const int*   idx   = (const int*)  d_in[2];
    const float* W1    = (const float*)d_in[3];
    const float* b1    = (const float*)d_in[4];
    const float* W2    = (const float*)d_in[5];
    const float* b2    = (const float*)d_in[6];
    const float* gamma = (const float*)d_in[7];
    const float* beta  = (const float*)d_in[8];
    float*       out   = (float*)d_out;

    detect_idx_kernel<<<1, 32>>>(idx);
    precompute_kernel<<<NNODE / PN, 128>>>(h, W1, b1);
    edgeconv_kernel<<<NNODE / PBN, 128>>>(pos, idx, W1, W2, b2, gamma, beta, out);
}

// round 7
// speedup vs baseline: 1.5750x; 1.0363x over previous
#include <cuda_runtime.h>
#include <math.h>

#define BB   8
#define NN   2048
#define KK   16
#define CIN  128
#define HID  128
#define COUT 128
#define NNODE (BB * NN)
#define PN   8     // nodes per block in precompute
#define PBN  2     // nodes per block in main kernel
#define ROWP 20    // padded x1t row length (floats)

// scratch: per-node projections  A = h@(W1a-W1b)+b1,  U = h@W1b
__device__ float g_A[NNODE * HID];
__device__ float g_U[NNODE * HID];
__device__ int   g_idx_is64;

// ---- f32x2 packed-math helpers ----
__device__ __forceinline__ unsigned long long ffma2(unsigned long long a,
                                                    unsigned long long b,
                                                    unsigned long long c) {
    unsigned long long d;
    asm("fma.rn.f32x2 %0, %1, %2, %3;" : "=l"(d) : "l"(a), "l"(b), "l"(c));
    return d;
}
__device__ __forceinline__ unsigned long long pack2(float lo, float hi) {
    unsigned long long v;
    asm("mov.b64 %0, {%1, %2};" : "=l"(v) : "f"(lo), "f"(hi));
    return v;
}
__device__ __forceinline__ float2 unpack2(unsigned long long v) {
    float2 r;
    asm("mov.b64 {%0, %1}, %2;" : "=f"(r.x), "=f"(r.y) : "l"(v));
    return r;
}

__device__ __forceinline__ float gelu_exact(float x) {
    return 0.5f * x * (1.0f + erff(x * 0.70710678118654752440f));
}

// ---------------------------------------------------------------------------
// Precompute A = h@(W1a-W1b)+b1,  U = h@W1b   (f32x2 packed along d).
// Block 0 additionally detects idx dtype (int64 vs int32) via warp ballot.
// ---------------------------------------------------------------------------
__global__ __launch_bounds__(128) void precompute_kernel(
    const float* __restrict__ h,
    const float* __restrict__ W1,
    const float* __restrict__ b1,
    const int*   __restrict__ idx_raw)
{
    __shared__ float hs[PN][CIN];
    const int t     = threadIdx.x;
    const int node0 = blockIdx.x * PN;

    if (blockIdx.x == 0 && t < 32) {
        int nz = (idx_raw[2 * t + 1] != 0) | (idx_raw[2 * (t + 32) + 1] != 0);
        unsigned m = __ballot_sync(0xffffffffu, nz);
        if (t == 0) g_idx_is64 = (m == 0u);
    }

    #pragma unroll
    for (int i = 0; i < PN; ++i)
        hs[i][t] = h[(size_t)(node0 + i) * CIN + t];
    __syncthreads();

    unsigned long long accA[PN], accU[PN];
    #pragma unroll
    for (int i = 0; i < PN; ++i) { accA[i] = 0ull; accU[i] = 0ull; }

    #pragma unroll 2
    for (int dd = 0; dd < CIN / 4; ++dd) {
        const int d0 = 4 * dd;
        float w1a[4], w1b[4];
        #pragma unroll
        for (int j = 0; j < 4; ++j) {
            w1a[j] = W1[(d0 + j) * HID + t];
            w1b[j] = W1[(CIN + d0 + j) * HID + t];
        }
        const unsigned long long wa01 = pack2(w1a[0] - w1b[0], w1a[1] - w1b[1]);
        const unsigned long long wa23 = pack2(w1a[2] - w1b[2], w1a[3] - w1b[3]);
        const unsigned long long wb01 = pack2(w1b[0], w1b[1]);
        const unsigned long long wb23 = pack2(w1b[2], w1b[3]);
        #pragma unroll
        for (int i = 0; i < PN; ++i) {
            const ulonglong2 m2 = *reinterpret_cast<const ulonglong2*>(&hs[i][d0]);
            accA[i] = ffma2(m2.x, wa01, accA[i]);
            accA[i] = ffma2(m2.y, wa23, accA[i]);
            accU[i] = ffma2(m2.x, wb01, accU[i]);
            accU[i] = ffma2(m2.y, wb23, accU[i]);
        }
    }
    const float bv = b1[t];
    #pragma unroll
    for (int i = 0; i < PN; ++i) {
        const float2 a2 = unpack2(accA[i]);
        const float2 u2 = unpack2(accU[i]);
        g_A[(size_t)(node0 + i) * HID + t] = a2.x + a2.y + bv;
        g_U[(size_t)(node0 + i) * HID + t] = u2.x + u2.y;
    }
}

// ---------------------------------------------------------------------------
// Main kernel: 2 nodes per block (128 threads).
// Phase A (thread = channel d): x1 transposed, k-major: x1t[nn][d][k].
// Phase B (64 threads per node): thread owns 2 cols x ALL 16 k, FFMA2 over
//         k-pairs; max over k via gelu-unimodality (min/max reduce, 2 gelu);
//         2-warp LayerNorm.
// ---------------------------------------------------------------------------
__global__ __launch_bounds__(128, 6) void edgeconv_kernel(
    const float* __restrict__ pos,
    const int*   __restrict__ idx_raw,
    const float* __restrict__ W1,      // rows 256..258 (rel weights)
    const float* __restrict__ W2,      // (HID, COUT) row-major
    const float* __restrict__ b2,
    const float* __restrict__ gamma,
    const float* __restrict__ beta,
    float*       __restrict__ out)
{
    __shared__ float x1t[PBN][HID][ROWP];   // 20 KB
    __shared__ int   jidx[PBN][KK];
    __shared__ float rel_s[PBN][KK][4];
    __shared__ float red_s[PBN][2][2];      // [node][stat][warp-in-node]

    const int t     = threadIdx.x;
    const int node0 = blockIdx.x * PBN;

    // ---- neighbor indices ----
    if (t < PBN * KK) {
        const int nn = t >> 4, k = t & 15;
        const int is64 = g_idx_is64;
        long e = (long)(node0 + nn) * KK + k;
        jidx[nn][k] = is64 ? idx_raw[2 * e] : idx_raw[e];
    }
    __syncthreads();

    // ---- relative positions ----
    if (t < PBN * 3 * KK) {
        const int nn = t / (3 * KK);
        const int r  = t - nn * 3 * KK;
        const int k  = r / 3, c = r - 3 * k;
        const int node = node0 + nn;
        const int b = node >> 11, n = node & (NN - 1);
        const float* pb = pos + (size_t)b * NN * 3;
        rel_s[nn][k][c] = pb[jidx[nn][k] * 3 + c] - pb[n * 3 + c];
    }
    __syncthreads();

    // ---- phase A: x1t (thread t = channel d) ----
    const float wc0 = W1[(2 * CIN + 0) * HID + t];
    const float wc1 = W1[(2 * CIN + 1) * HID + t];
    const float wc2 = W1[(2 * CIN + 2) * HID + t];

    #pragma unroll
    for (int nn = 0; nn < PBN; ++nn) {
        const int node = node0 + nn;
        const int b = node >> 11;
        const float a = g_A[(size_t)node * HID + t];
        float v[KK];
        #pragma unroll
        for (int k = 0; k < KK; ++k) {
            const float uk = g_U[((size_t)b * NN + jidx[nn][k]) * HID + t];
            float x = a + uk;
            x = fmaf(rel_s[nn][k][0], wc0, x);
            x = fmaf(rel_s[nn][k][1], wc1, x);
            x = fmaf(rel_s[nn][k][2], wc2, x);
            v[k] = gelu_exact(x);
        }
        #pragma unroll
        for (int g = 0; g < 4; ++g)
            *reinterpret_cast<float4*>(&x1t[nn][t][4 * g]) =
                make_float4(v[4 * g], v[4 * g + 1], v[4 * g + 2], v[4 * g + 3]);
    }
    __syncthreads();

    // ---- phase B: GEMM2, 64 threads per node, 2 cols x 16 k per thread ----
    const int nn   = t >> 6;
    const int u    = t & 63;
    const int c0   = 2 * u;
    const int node = node0 + nn;

    unsigned long long acc[8][2];     // [k-pair][col]
    #pragma unroll
    for (int kp = 0; kp < 8; ++kp) { acc[kp][0] = 0ull; acc[kp][1] = 0ull; }

    #pragma unroll 2
    for (int dd = 0; dd < HID / 4; ++dd) {
        #pragma unroll
        for (int j = 0; j < 4; ++j) {
            const int d = 4 * dd + j;
            const float2 w = *reinterpret_cast<const float2*>(&W2[d * COUT + c0]);
            const unsigned long long wpA = pack2(w.x, w.x);
            const unsigned long long wpB = pack2(w.y, w.y);
            const ulonglong2* row = reinterpret_cast<const ulonglong2*>(&x1t[nn][d][0]);
            #pragma unroll
            for (int j2 = 0; j2 < 4; ++j2) {
                const ulonglong2 p = row[j2];
                acc[2 * j2 + 0][0] = ffma2(p.x, wpA, acc[2 * j2 + 0][0]);
                acc[2 * j2 + 0][1] = ffma2(p.x, wpB, acc[2 * j2 + 0][1]);
                acc[2 * j2 + 1][0] = ffma2(p.y, wpA, acc[2 * j2 + 1][0]);
                acc[2 * j2 + 1][1] = ffma2(p.y, wpB, acc[2 * j2 + 1][1]);
            }
        }
    }

    // ---- epilogue: min/max over 16 k, then gelu at the two extremes only.
    // gelu is unimodal (single min at x*≈-0.7518), so
    // max_k gelu(x_k + b) = max(gelu(min_k x_k + b), gelu(max_k x_k + b)).
    float lo0 =  INFINITY, hi0 = -INFINITY;
    float lo1 =  INFINITY, hi1 = -INFINITY;
    #pragma unroll
    for (int kp = 0; kp < 8; ++kp) {
        const float2 p0 = unpack2(acc[kp][0]);
        const float2 p1 = unpack2(acc[kp][1]);
        lo0 = fminf(lo0, fminf(p0.x, p0.y));
        hi0 = fmaxf(hi0, fmaxf(p0.x, p0.y));
        lo1 = fminf(lo1, fminf(p1.x, p1.y));
        hi1 = fmaxf(hi1, fmaxf(p1.x, p1.y));
    }
    const float2 bv = *reinterpret_cast<const float2*>(&b2[c0]);
    const float v0 = fmaxf(gelu_exact(lo0 + bv.x), gelu_exact(hi0 + bv.x));
    const float v1 = fmaxf(gelu_exact(lo1 + bv.y), gelu_exact(hi1 + bv.y));

    // ---- LayerNorm over 128 channels = 64 threads (2 warps) per node ----
    const int winn = (t >> 5) & 1;
    float s = v0 + v1;
    #pragma unroll
    for (int o = 16; o > 0; o >>= 1) s += __shfl_xor_sync(0xffffffffu, s, o);
    if ((t & 31) == 0) red_s[nn][0][winn] = s;
    __syncthreads();
    const float mean = (red_s[nn][0][0] + red_s[nn][0][1]) * (1.0f / COUT);

    const float d0v = v0 - mean, d1v = v1 - mean;
    float q = d0v * d0v + d1v * d1v;
    #pragma unroll
    for (int o = 16; o > 0; o >>= 1) q += __shfl_xor_sync(0xffffffffu, q, o);
    if ((t & 31) == 0) red_s[nn][1][winn] = q;
    __syncthreads();
    const float var  = (red_s[nn][1][0] + red_s[nn][1][1]) * (1.0f / COUT);
    const float rstd = rsqrtf(var + 1e-5f);

    const float2 g2 = *reinterpret_cast<const float2*>(&gamma[c0]);
    const float2 be2 = *reinterpret_cast<const float2*>(&beta[c0]);
    float2 o2;
    o2.x = d0v * rstd * g2.x + be2.x;
    o2.y = d1v * rstd * g2.y + be2.y;
    *reinterpret_cast<float2*>(&out[(size_t)node * COUT + c0]) = o2;
}

extern "C" void kernel_launch(void* const* d_in, const int* in_sizes, int n_in,
                              void* d_out, int out_size) {
    const float* h     = (const float*)d_in[0];
    const float* pos   = (const float*)d_in[1];
    const int*   idx   = (const int*)  d_in[2];
    const float* W1    = (const float*)d_in[3];
    const float* b1    = (const float*)d_in[4];
    const float* W2    = (const float*)d_in[5];
    const float* b2    = (const float*)d_in[6];
    const float* gamma = (const float*)d_in[7];
    const float* beta  = (const float*)d_in[8];
    float*       out   = (float*)d_out;

    precompute_kernel<<<NNODE / PN, 128>>>(h, W1, b1, idx);
    edgeconv_kernel<<<NNODE / PBN, 128>>>(pos, idx, W1, W2, b2, gamma, beta, out);
}